// round 4
// baseline (speedup 1.0000x reference)
#include <cuda_runtime.h>
#include <math.h>

// ---------------------------------------------------------------------------
// Problem constants
// ---------------------------------------------------------------------------
#define BB   2
#define LL   1024
#define DD   768
#define EE   1536
#define NSTATE 16
#define RR   48
#define KCONV 4
#define NLAYER 4
#define NCLS 5
#define XDIM 80              // R + 2N
#define ROWS (BB*LL)         // 2048
#define SPLITK_X 12          // split-K factor for the N=80 GEMM

// ---------------------------------------------------------------------------
// Scratch (static device memory; allocation at runtime is forbidden)
// ---------------------------------------------------------------------------
__device__ float g_h   [ROWS*DD];        //  6.3 MB residual stream
__device__ float g_hn  [ROWS*DD];        //  6.3 MB rmsnorm output
__device__ float g_proj[ROWS*2*EE];      // 25.2 MB u_raw | gate
__device__ float g_u   [ROWS*EE];        // 12.6 MB conv+silu output
__device__ float g_xdbc[ROWS*XDIM];      //  0.7 MB
__device__ float g_xpart[SPLITK_X*ROWS*XDIM]; // 7.9 MB split-K partials
__device__ float g_dt  [ROWS*EE];        // 12.6 MB
__device__ float g_y   [ROWS*EE];        // 12.6 MB
__device__ float g_pooled[BB*DD];

// ---------------------------------------------------------------------------
// Input projection: h = x @ proj_w^T + proj_b   (x: 2048x12, proj_w: 768x12)
// ---------------------------------------------------------------------------
__global__ void k_proj(const float* __restrict__ x,
                       const float* __restrict__ w,
                       const float* __restrict__ b,
                       float* __restrict__ h)
{
    int idx = blockIdx.x * blockDim.x + threadIdx.x;
    if (idx >= ROWS * DD) return;
    int r = idx / DD, d = idx % DD;
    const float* xr = x + r * 12;
    const float* wr = w + d * 12;
    float acc = b[d];
#pragma unroll
    for (int j = 0; j < 12; j++) acc = fmaf(xr[j], wr[j], acc);
    h[idx] = acc;
}

// ---------------------------------------------------------------------------
// RMSNorm over last dim (D=768). One block per row.
// ---------------------------------------------------------------------------
__global__ void k_rms(const float* __restrict__ x,
                      const float* __restrict__ w,
                      float* __restrict__ o)
{
    int r = blockIdx.x;
    const float* xr = x + (size_t)r * DD;
    float s = 0.f;
    for (int d = threadIdx.x; d < DD; d += 256) { float v = xr[d]; s = fmaf(v, v, s); }
#pragma unroll
    for (int off = 16; off; off >>= 1) s += __shfl_xor_sync(0xffffffffu, s, off);
    __shared__ float red[8];
    __shared__ float rs_s;
    if ((threadIdx.x & 31) == 0) red[threadIdx.x >> 5] = s;
    __syncthreads();
    if (threadIdx.x < 32) {
        float t = (threadIdx.x < 8) ? red[threadIdx.x] : 0.f;
#pragma unroll
        for (int off = 4; off; off >>= 1) t += __shfl_xor_sync(0xffffffffu, t, off);
        if (threadIdx.x == 0) rs_s = rsqrtf(t / (float)DD + 1e-5f);
    }
    __syncthreads();
    float rs = rs_s;
    for (int d = threadIdx.x; d < DD; d += 256)
        o[(size_t)r * DD + d] = xr[d] * rs * w[d];
}

// ---------------------------------------------------------------------------
// Tiled FP32 GEMM (NT): C[M,N] (op)= A[M,K] * W[N,K]^T
//   A row stride = lda (K-contiguous), W row stride = K, C row stride = ldc.
//   MODE 0: C = acc
//   MODE 1: C = softplus(acc + bias[n])
//   MODE 2: C += acc          (residual accumulate, in place)
//   Split-K: gridDim.z chunks of kchunk; each z writes C + z*M*ldc (MODE 0 only).
//   Assumes M % 128 == 0 (true for all call sites: M = 2048).
// ---------------------------------------------------------------------------
template <int MODE>
__global__ __launch_bounds__(256, 2)
void gemm_nt(const float* __restrict__ A, int lda,
             const float* __restrict__ W,
             const float* __restrict__ bias,
             float* __restrict__ C, int ldc,
             int M, int N, int K, int kchunk)
{
    const int BM = 128, BN = 128, BK = 16;
    __shared__ float As[BK][BM + 4];
    __shared__ float Ws[BK][BN + 4];

    int tid = threadIdx.x;
    int tx = tid & 15, ty = tid >> 4;
    int rowA0 = blockIdx.y * BM;
    int rowW0 = blockIdx.x * BN;

    if (gridDim.z > 1) C += (size_t)blockIdx.z * (size_t)M * (size_t)ldc;
    int kb = blockIdx.z * kchunk;
    int ke = kb + kchunk;

    float acc[8][8];
#pragma unroll
    for (int i = 0; i < 8; i++)
#pragma unroll
        for (int j = 0; j < 8; j++) acc[i][j] = 0.f;

    int lrow = tid >> 2;          // 0..63
    int lcol = (tid & 3) * 4;     // 0,4,8,12

    for (int k0 = kb; k0 < ke; k0 += BK) {
#pragma unroll
        for (int jj = 0; jj < 2; jj++) {
            int r = lrow + 64 * jj;
            // A tile (rows always in range: M multiple of 128)
            const float4 va = *(const float4*)(A + (size_t)(rowA0 + r) * lda + k0 + lcol);
            As[lcol + 0][r] = va.x; As[lcol + 1][r] = va.y;
            As[lcol + 2][r] = va.z; As[lcol + 3][r] = va.w;
            // W tile (guard rows against N)
            int gw = rowW0 + r;
            float4 vw = make_float4(0.f, 0.f, 0.f, 0.f);
            if (gw < N) vw = *(const float4*)(W + (size_t)gw * K + k0 + lcol);
            Ws[lcol + 0][r] = vw.x; Ws[lcol + 1][r] = vw.y;
            Ws[lcol + 2][r] = vw.z; Ws[lcol + 3][r] = vw.w;
        }
        __syncthreads();
#pragma unroll
        for (int k = 0; k < BK; k++) {
            float a[8], b[8];
#pragma unroll
            for (int i = 0; i < 4; i++) {
                a[i]     = As[k][ty * 4 + i];
                a[i + 4] = As[k][64 + ty * 4 + i];
                b[i]     = Ws[k][tx * 4 + i];
                b[i + 4] = Ws[k][64 + tx * 4 + i];
            }
#pragma unroll
            for (int i = 0; i < 8; i++)
#pragma unroll
                for (int j = 0; j < 8; j++)
                    acc[i][j] = fmaf(a[i], b[j], acc[i][j]);
        }
        __syncthreads();
    }

#pragma unroll
    for (int i = 0; i < 8; i++) {
        int mrow = rowA0 + ((i < 4) ? (ty * 4 + i) : (64 + ty * 4 + i - 4));
#pragma unroll
        for (int j = 0; j < 8; j++) {
            int ncol = rowW0 + ((j < 4) ? (tx * 4 + j) : (64 + tx * 4 + j - 4));
            if (ncol < N) {
                float v = acc[i][j];
                float* cp = C + (size_t)mrow * ldc + ncol;
                if (MODE == 1) {
                    v += bias[ncol];
                    v = fmaxf(v, 0.f) + log1pf(__expf(-fabsf(v)));  // softplus
                }
                if (MODE == 2) v += *cp;
                *cp = v;
            }
        }
    }
}

// ---------------------------------------------------------------------------
// Reduce split-K partials for xdbc
// ---------------------------------------------------------------------------
__global__ void k_reduce_x(const float* __restrict__ part, float* __restrict__ out)
{
    int idx = blockIdx.x * blockDim.x + threadIdx.x;
    if (idx >= ROWS * XDIM) return;
    float s = 0.f;
#pragma unroll
    for (int z = 0; z < SPLITK_X; z++) s += part[(size_t)z * ROWS * XDIM + idx];
    out[idx] = s;
}

// ---------------------------------------------------------------------------
// Depthwise causal conv (K=4) + SiLU.
// Reads u_raw = proj[:, :, 0:E]; writes g_u (B,L,E)
// ---------------------------------------------------------------------------
__global__ void k_conv(const float* __restrict__ proj,
                       const float* __restrict__ cw,
                       const float* __restrict__ cb,
                       float* __restrict__ u)
{
    int idx = blockIdx.x * blockDim.x + threadIdx.x;
    if (idx >= ROWS * EE) return;
    int e = idx % EE;
    int r = idx / EE;        // b*L + t
    int t = r % LL;
    float acc = cb[e];
#pragma unroll
    for (int k = 0; k < KCONV; k++) {
        int tt = t - (KCONV - 1) + k;
        if (tt >= 0)
            acc = fmaf(cw[e * KCONV + k],
                       proj[(size_t)(r - (KCONV - 1) + k) * (2 * EE) + e], acc);
    }
    u[idx] = acc / (1.f + __expf(-acc));   // silu
}

// ---------------------------------------------------------------------------
// Selective scan. 16 lanes per (b,e) group; lane = state index n.
//   h_n <- h_n * exp(dt*A_n) + dt*B_n*u ;  y = sum_n h_n*C_n + u*Dp
//   y  <- y * silu(gate)
// ---------------------------------------------------------------------------
__global__ void k_scan(const float* __restrict__ u,
                       const float* __restrict__ dt,
                       const float* __restrict__ xdbc,
                       const float* __restrict__ A_log,
                       const float* __restrict__ Dp,
                       const float* __restrict__ proj,   // gate at [.., E + e]
                       float* __restrict__ y)
{
    int gid  = (blockIdx.x * blockDim.x + threadIdx.x) >> 4;
    int lane = threadIdx.x & 15;
    if (gid >= BB * EE) return;
    int b = gid / EE, e = gid % EE;

    float An   = -__expf(A_log[e * NSTATE + lane]);
    float dval = Dp[e];
    float h = 0.f;

    const float* dtp = dt   + (size_t)b * LL * EE + e;
    const float* up  = u    + (size_t)b * LL * EE + e;
    const float* xp  = xdbc + (size_t)b * LL * XDIM;
    const float* gp  = proj + (size_t)b * LL * 2 * EE + EE + e;
    float*       yp  = y    + (size_t)b * LL * EE + e;

    for (int t = 0; t < LL; t++) {
        float dtv = __ldg(dtp + (size_t)t * EE);
        float uv  = __ldg(up  + (size_t)t * EE);
        float Bn  = __ldg(xp + (size_t)t * XDIM + RR + lane);
        float Cn  = __ldg(xp + (size_t)t * XDIM + RR + NSTATE + lane);
        float dA  = __expf(dtv * An);
        h = fmaf(h, dA, dtv * Bn * uv);
        float yv = h * Cn;
        yv += __shfl_xor_sync(0xffffffffu, yv, 1);
        yv += __shfl_xor_sync(0xffffffffu, yv, 2);
        yv += __shfl_xor_sync(0xffffffffu, yv, 4);
        yv += __shfl_xor_sync(0xffffffffu, yv, 8);
        if (lane == 0) {
            float g  = __ldg(gp + (size_t)t * 2 * EE);
            float sg = g / (1.f + __expf(-g));
            yp[(size_t)t * EE] = (yv + uv * dval) * sg;
        }
    }
}

// ---------------------------------------------------------------------------
// Mean-pool over L (after final rmsnorm)
// ---------------------------------------------------------------------------
__global__ void k_pool(const float* __restrict__ hn, float* __restrict__ pooled)
{
    int idx = blockIdx.x * blockDim.x + threadIdx.x;
    if (idx >= BB * DD) return;
    int b = idx / DD, d = idx % DD;
    float s = 0.f;
    for (int t = 0; t < LL; t++) s += hn[(size_t)(b * LL + t) * DD + d];
    pooled[idx] = s * (1.f / (float)LL);
}

// ---------------------------------------------------------------------------
// Classifier: out[b,c] = pooled[b] . cls_w[c] + cls_b[c]    (10 outputs)
// ---------------------------------------------------------------------------
__global__ void k_cls(const float* __restrict__ pooled,
                      const float* __restrict__ w,
                      const float* __restrict__ b,
                      float* __restrict__ out)
{
    int wid  = threadIdx.x >> 5;
    int lane = threadIdx.x & 31;
    if (wid >= BB * NCLS) return;
    int bb = wid / NCLS, c = wid % NCLS;
    float s = 0.f;
    for (int d = lane; d < DD; d += 32)
        s = fmaf(pooled[bb * DD + d], w[c * DD + d], s);
#pragma unroll
    for (int off = 16; off; off >>= 1) s += __shfl_xor_sync(0xffffffffu, s, off);
    if (lane == 0) out[bb * NCLS + c] = s + b[c];
}

// ---------------------------------------------------------------------------
// kernel_launch — graph-capturable, allocation-free.
// Input order (metadata): x, proj_w, proj_b, norm_w, in_w, conv_w, conv_b,
//   xproj_w, dt_w, dt_b, A_log, D_param, out_w, fnorm_w, cls_w, cls_b
// ---------------------------------------------------------------------------
extern "C" void kernel_launch(void* const* d_in, const int* in_sizes, int n_in,
                              void* d_out, int out_size)
{
    const float* x       = (const float*)d_in[0];
    const float* proj_w  = (const float*)d_in[1];
    const float* proj_b  = (const float*)d_in[2];
    const float* norm_w  = (const float*)d_in[3];
    const float* in_w    = (const float*)d_in[4];
    const float* conv_w  = (const float*)d_in[5];
    const float* conv_b  = (const float*)d_in[6];
    const float* xproj_w = (const float*)d_in[7];
    const float* dt_w    = (const float*)d_in[8];
    const float* dt_b    = (const float*)d_in[9];
    const float* A_log   = (const float*)d_in[10];
    const float* D_param = (const float*)d_in[11];
    const float* out_w   = (const float*)d_in[12];
    const float* fnorm_w = (const float*)d_in[13];
    const float* cls_w   = (const float*)d_in[14];
    const float* cls_b   = (const float*)d_in[15];
    float* out = (float*)d_out;

    float *h_, *hn_, *proj_, *u_, *xdbc_, *xpart_, *dt_, *y_, *pooled_;
    cudaGetSymbolAddress((void**)&h_,      g_h);
    cudaGetSymbolAddress((void**)&hn_,     g_hn);
    cudaGetSymbolAddress((void**)&proj_,   g_proj);
    cudaGetSymbolAddress((void**)&u_,      g_u);
    cudaGetSymbolAddress((void**)&xdbc_,   g_xdbc);
    cudaGetSymbolAddress((void**)&xpart_,  g_xpart);
    cudaGetSymbolAddress((void**)&dt_,     g_dt);
    cudaGetSymbolAddress((void**)&y_,      g_y);
    cudaGetSymbolAddress((void**)&pooled_, g_pooled);

    // h = x @ proj_w^T + proj_b
    k_proj<<<(ROWS * DD + 255) / 256, 256>>>(x, proj_w, proj_b, h_);

    for (int i = 0; i < NLAYER; i++) {
        // hn = rmsnorm(h, norm_w[i])
        k_rms<<<ROWS, 256>>>(h_, norm_w + i * DD, hn_);

        // proj = hn @ in_w[i]^T  (2048 x 3072, K=768)
        {
            dim3 g(2 * EE / 128, ROWS / 128);
            gemm_nt<0><<<g, 256>>>(hn_, DD, in_w + (size_t)i * 2 * EE * DD,
                                   nullptr, proj_, 2 * EE,
                                   ROWS, 2 * EE, DD, DD);
        }

        // u = silu(causal_conv(proj[:,:,:E]))
        k_conv<<<(ROWS * EE + 255) / 256, 256>>>(proj_, conv_w + i * EE * KCONV,
                                                 conv_b + i * EE, u_);

        // xdbc = u @ xproj_w[i]^T  (2048 x 80, K=1536) — split-K x12
        {
            dim3 g(1, ROWS / 128, SPLITK_X);
            gemm_nt<0><<<g, 256>>>(u_, EE, xproj_w + (size_t)i * XDIM * EE,
                                   nullptr, xpart_, XDIM,
                                   ROWS, XDIM, EE, EE / SPLITK_X);
            k_reduce_x<<<(ROWS * XDIM + 255) / 256, 256>>>(xpart_, xdbc_);
        }

        // dt = softplus(xdbc[:,:,:R] @ dt_w[i]^T + dt_b[i])  (2048 x 1536, K=48)
        {
            dim3 g(EE / 128, ROWS / 128);
            gemm_nt<1><<<g, 256>>>(xdbc_, XDIM, dt_w + (size_t)i * EE * RR,
                                   dt_b + i * EE, dt_, EE,
                                   ROWS, EE, RR, RR);
        }

        // selective scan (+ D skip + gate silu)
        k_scan<<<(BB * EE * 16) / 256, 256>>>(u_, dt_, xdbc_,
                                              A_log + i * EE * NSTATE,
                                              D_param + i * EE, proj_, y_);

        // h = h + y @ out_w[i]^T  (2048 x 768, K=1536), residual in place
        {
            dim3 g(DD / 128, ROWS / 128);
            gemm_nt<2><<<g, 256>>>(y_, EE, out_w + (size_t)i * DD * EE,
                                   nullptr, h_, DD,
                                   ROWS, DD, EE, EE);
        }
    }

    // final rmsnorm, mean pool, classifier
    k_rms<<<ROWS, 256>>>(h_, fnorm_w, hn_);
    k_pool<<<(BB * DD + 255) / 256, 256>>>(hn_, pooled_);
    k_cls<<<1, 320>>>(pooled_, cls_w, cls_b, out);
}

// round 6
// speedup vs baseline: 1.2361x; 1.2361x over previous
#include <cuda_runtime.h>
#include <cuda_bf16.h>
#include <math.h>
#include <stdint.h>

// ---------------------------------------------------------------------------
// Problem constants
// ---------------------------------------------------------------------------
#define BB   2
#define LL   1024
#define DD   768
#define EE   1536
#define NSTATE 16
#define RR   48
#define KCONV 4
#define NLAYER 4
#define NCLS 5
#define XDIM 80              // R + 2N
#define ROWS (BB*LL)         // 2048
#define SPLITK_X 12          // split-K factor for the N=80 GEMM

// ---------------------------------------------------------------------------
// Scratch (static device memory; allocation at runtime is forbidden)
// ---------------------------------------------------------------------------
__device__ float g_h   [ROWS*DD];
__device__ float g_hn  [ROWS*DD];
__device__ float g_proj[ROWS*2*EE];
__device__ float g_u   [ROWS*EE];
__device__ float g_xdbc[ROWS*XDIM];
__device__ float g_xpart[SPLITK_X*ROWS*XDIM];
__device__ float g_dt  [ROWS*EE];
__device__ float g_y   [ROWS*EE];
__device__ float g_pooled[BB*DD];

// ---------------------------------------------------------------------------
// Helpers
// ---------------------------------------------------------------------------
__device__ __forceinline__ uint32_t smem_u32(const void* p) {
    uint32_t a;
    asm("{ .reg .u64 t; cvta.to.shared.u64 t, %1; cvt.u32.u64 %0, t; }"
        : "=r"(a) : "l"(p));
    return a;
}

__device__ __forceinline__ void ldm_x4(uint32_t* r, uint32_t addr) {
    asm volatile("ldmatrix.sync.aligned.m8n8.x4.shared.b16 {%0,%1,%2,%3}, [%4];"
                 : "=r"(r[0]), "=r"(r[1]), "=r"(r[2]), "=r"(r[3])
                 : "r"(addr));
}

__device__ __forceinline__ void mma16816(float* c, const uint32_t* a,
                                         const uint32_t* b) {
    asm volatile(
        "mma.sync.aligned.m16n8k16.row.col.f32.bf16.bf16.f32 "
        "{%0,%1,%2,%3}, {%4,%5,%6,%7}, {%8,%9}, {%0,%1,%2,%3};"
        : "+f"(c[0]), "+f"(c[1]), "+f"(c[2]), "+f"(c[3])
        : "r"(a[0]), "r"(a[1]), "r"(a[2]), "r"(a[3]), "r"(b[0]), "r"(b[1]));
}

// ---------------------------------------------------------------------------
// Tensor-core GEMM via mma.sync (bf16x3 fp32 emulation), NT:
//   C[M,N] (op)= A[M,K] * W[N,K]^T ; fp32 in global memory.
//   MODE 0: C = acc ; MODE 2: C += acc (residual).
//   M,N multiples of 128; K multiple of 32; 16B-aligned rows.
// CTA tile 128x128, 256 threads (8 warps, 2x4), warp tile 64x32.
// Smem per buffer: 4 tiles (Ahi,Alo,Whi,Wlo) of 128 rows x 80B = 40960B,
// double buffered -> 81920B dynamic smem.
// ---------------------------------------------------------------------------
#define TILE_B   10240      // one bf16 tile: 128 rows x 80 bytes
#define BUF_B    (4*TILE_B) // 40960
#define MMA_SMEM (2*BUF_B)  // 81920

template <int MODE>
__global__ __launch_bounds__(256)
void gemm_mma(const float* __restrict__ A, int lda,
              const float* __restrict__ W,
              float* __restrict__ C, int ldc, int K)
{
    extern __shared__ char smem[];
    const int tid  = threadIdx.x;
    const int wid  = tid >> 5;
    const int lane = tid & 31;
    const int wm   = wid & 1;        // warp row (2)
    const int wn   = wid >> 1;       // warp col (4)
    const int rowA0 = blockIdx.y * 128;
    const int rowW0 = blockIdx.x * 128;
    const uint32_t sb = smem_u32(smem);

    float acc[4][4][4];
#pragma unroll
    for (int i = 0; i < 4; i++)
#pragma unroll
        for (int j = 0; j < 4; j++)
#pragma unroll
            for (int q = 0; q < 4; q++) acc[i][j][q] = 0.f;

    // ldmatrix per-lane offsets within a tile (bytes)
    const uint32_t aoff = (uint32_t)((lane & 15) * 80 + (lane >> 4) * 16);
    const uint32_t boff = (uint32_t)(((((lane >> 4) << 3) | (lane & 7))) * 80 +
                                     ((lane >> 3) & 1) * 16);

    const int nch = K >> 5;          // 32-wide K chunks

    const float* Ab = A + (size_t)rowA0 * lda;
    const float* Wb = W + (size_t)rowW0 * K;

    float4 pa[4], pw[4];
    // prefetch chunk 0
#pragma unroll
    for (int it = 0; it < 4; ++it) {
        int idx = tid + (it << 8);
        int r = idx >> 3, c = idx & 7;
        pa[it] = *(const float4*)(Ab + (size_t)r * lda + (c << 2));
        pw[it] = *(const float4*)(Wb + (size_t)r * K   + (c << 2));
    }

    for (int ch = 0; ch < nch; ++ch) {
        const uint32_t tb = sb + (uint32_t)((ch & 1) * BUF_B);
        char* tchar = smem + (ch & 1) * BUF_B;

        // ---- STS: hi/lo split of A and W tiles ----
#pragma unroll
        for (int it = 0; it < 4; ++it) {
            int idx = tid + (it << 8);
            int r = idx >> 3, c = idx & 7;
            uint32_t off = (uint32_t)(r * 80 + (c << 3));
#pragma unroll
            for (int half = 0; half < 2; ++half) {
                float4 v = half ? pw[it] : pa[it];
                __nv_bfloat16 h0 = __float2bfloat16(v.x);
                __nv_bfloat16 h1 = __float2bfloat16(v.y);
                __nv_bfloat16 h2 = __float2bfloat16(v.z);
                __nv_bfloat16 h3 = __float2bfloat16(v.w);
                __nv_bfloat16 l0 = __float2bfloat16(v.x - __bfloat162float(h0));
                __nv_bfloat16 l1 = __float2bfloat16(v.y - __bfloat162float(h1));
                __nv_bfloat16 l2 = __float2bfloat16(v.z - __bfloat162float(h2));
                __nv_bfloat16 l3 = __float2bfloat16(v.w - __bfloat162float(h3));
                uint2 H, L;
                H.x = (uint32_t)__bfloat16_as_ushort(h0) |
                      ((uint32_t)__bfloat16_as_ushort(h1) << 16);
                H.y = (uint32_t)__bfloat16_as_ushort(h2) |
                      ((uint32_t)__bfloat16_as_ushort(h3) << 16);
                L.x = (uint32_t)__bfloat16_as_ushort(l0) |
                      ((uint32_t)__bfloat16_as_ushort(l1) << 16);
                L.y = (uint32_t)__bfloat16_as_ushort(l2) |
                      ((uint32_t)__bfloat16_as_ushort(l3) << 16);
                int base = half * (2 * TILE_B);
                *(uint2*)(tchar + base + off)          = H;
                *(uint2*)(tchar + base + TILE_B + off) = L;
            }
        }
        __syncthreads();

        // ---- prefetch next chunk (overlaps with MMA below) ----
        if (ch + 1 < nch) {
            int k0 = (ch + 1) << 5;
#pragma unroll
            for (int it = 0; it < 4; ++it) {
                int idx = tid + (it << 8);
                int r = idx >> 3, c = idx & 7;
                pa[it] = *(const float4*)(Ab + (size_t)r * lda + k0 + (c << 2));
                pw[it] = *(const float4*)(Wb + (size_t)r * K   + k0 + (c << 2));
            }
        }

        // ---- MMA: 2 k16-steps x (4m x 4n) x 3 emulation terms ----
#pragma unroll
        for (int ks = 0; ks < 2; ++ks) {
            uint32_t ah[4][4], al[4][4], bh[4][2], bl[4][2];
#pragma unroll
            for (int i = 0; i < 4; ++i) {
                uint32_t base = tb + (uint32_t)((wm * 64 + i * 16) * 80) +
                                aoff + (uint32_t)(ks * 32);
                ldm_x4(ah[i], base);
                ldm_x4(al[i], base + TILE_B);
            }
#pragma unroll
            for (int j2 = 0; j2 < 2; ++j2) {
                uint32_t base = tb + 2 * TILE_B +
                                (uint32_t)((wn * 32 + j2 * 16) * 80) +
                                boff + (uint32_t)(ks * 32);
                uint32_t t[4];
                ldm_x4(t, base);
                bh[2 * j2][0] = t[0]; bh[2 * j2][1] = t[1];
                bh[2 * j2 + 1][0] = t[2]; bh[2 * j2 + 1][1] = t[3];
                ldm_x4(t, base + TILE_B);
                bl[2 * j2][0] = t[0]; bl[2 * j2][1] = t[1];
                bl[2 * j2 + 1][0] = t[2]; bl[2 * j2 + 1][1] = t[3];
            }
#pragma unroll
            for (int i = 0; i < 4; ++i)
#pragma unroll
                for (int j = 0; j < 4; ++j) {
                    mma16816(acc[i][j], ah[i], bh[j]);
                    mma16816(acc[i][j], ah[i], bl[j]);
                    mma16816(acc[i][j], al[i], bh[j]);
                }
        }
        __syncthreads();
    }

    // ---- epilogue: c-frag layout (t/4, 2*(t%4)) ----
    const int er = lane >> 2;
    const int ec = (lane & 3) * 2;
#pragma unroll
    for (int i = 0; i < 4; ++i) {
        int r0 = rowA0 + wm * 64 + i * 16 + er;
#pragma unroll
        for (int j = 0; j < 4; ++j) {
            int c0 = rowW0 + wn * 32 + j * 8 + ec;
            float* p0 = C + (size_t)r0 * ldc + c0;
            float* p1 = C + (size_t)(r0 + 8) * ldc + c0;
            float2 v0 = make_float2(acc[i][j][0], acc[i][j][1]);
            float2 v1 = make_float2(acc[i][j][2], acc[i][j][3]);
            if (MODE == 2) {
                float2 o0 = *(float2*)p0, o1 = *(float2*)p1;
                v0.x += o0.x; v0.y += o0.y;
                v1.x += o1.x; v1.y += o1.y;
            }
            *(float2*)p0 = v0;
            *(float2*)p1 = v1;
        }
    }
}

// ---------------------------------------------------------------------------
// Input projection: h = x @ proj_w^T + proj_b
// ---------------------------------------------------------------------------
__global__ void k_proj(const float* __restrict__ x,
                       const float* __restrict__ w,
                       const float* __restrict__ b,
                       float* __restrict__ h)
{
    int idx = blockIdx.x * blockDim.x + threadIdx.x;
    if (idx >= ROWS * DD) return;
    int r = idx / DD, d = idx % DD;
    const float* xr = x + r * 12;
    const float* wr = w + d * 12;
    float acc = b[d];
#pragma unroll
    for (int j = 0; j < 12; j++) acc = fmaf(xr[j], wr[j], acc);
    h[idx] = acc;
}

// ---------------------------------------------------------------------------
// RMSNorm over last dim (D=768). One block per row.
// ---------------------------------------------------------------------------
__global__ void k_rms(const float* __restrict__ x,
                      const float* __restrict__ w,
                      float* __restrict__ o)
{
    int r = blockIdx.x;
    const float* xr = x + (size_t)r * DD;
    float s = 0.f;
    for (int d = threadIdx.x; d < DD; d += 256) { float v = xr[d]; s = fmaf(v, v, s); }
#pragma unroll
    for (int off = 16; off; off >>= 1) s += __shfl_xor_sync(0xffffffffu, s, off);
    __shared__ float red[8];
    __shared__ float rs_s;
    if ((threadIdx.x & 31) == 0) red[threadIdx.x >> 5] = s;
    __syncthreads();
    if (threadIdx.x < 32) {
        float t = (threadIdx.x < 8) ? red[threadIdx.x] : 0.f;
#pragma unroll
        for (int off = 4; off; off >>= 1) t += __shfl_xor_sync(0xffffffffu, t, off);
        if (threadIdx.x == 0) rs_s = rsqrtf(t / (float)DD + 1e-5f);
    }
    __syncthreads();
    float rs = rs_s;
    for (int d = threadIdx.x; d < DD; d += 256)
        o[(size_t)r * DD + d] = xr[d] * rs * w[d];
}

// ---------------------------------------------------------------------------
// Tiled FP32 GEMM (NT) — for the small xdbc / dt GEMMs.
//   MODE 0: C = acc ; MODE 1: C = softplus(acc + bias[n])
//   Split-K: gridDim.z chunks; each z writes C + z*M*ldc (MODE 0).
// ---------------------------------------------------------------------------
template <int MODE>
__global__ __launch_bounds__(256, 2)
void gemm_nt(const float* __restrict__ A, int lda,
             const float* __restrict__ W,
             const float* __restrict__ bias,
             float* __restrict__ C, int ldc,
             int M, int N, int K, int kchunk)
{
    const int BM = 128, BN = 128, BK = 16;
    __shared__ float As[BK][BM + 4];
    __shared__ float Ws[BK][BN + 4];

    int tid = threadIdx.x;
    int tx = tid & 15, ty = tid >> 4;
    int rowA0 = blockIdx.y * BM;
    int rowW0 = blockIdx.x * BN;

    if (gridDim.z > 1) C += (size_t)blockIdx.z * (size_t)M * (size_t)ldc;
    int kb = blockIdx.z * kchunk;
    int ke = kb + kchunk;

    float acc[8][8];
#pragma unroll
    for (int i = 0; i < 8; i++)
#pragma unroll
        for (int j = 0; j < 8; j++) acc[i][j] = 0.f;

    int lrow = tid >> 2;
    int lcol = (tid & 3) * 4;

    for (int k0 = kb; k0 < ke; k0 += BK) {
#pragma unroll
        for (int jj = 0; jj < 2; jj++) {
            int r = lrow + 64 * jj;
            const float4 va = *(const float4*)(A + (size_t)(rowA0 + r) * lda + k0 + lcol);
            As[lcol + 0][r] = va.x; As[lcol + 1][r] = va.y;
            As[lcol + 2][r] = va.z; As[lcol + 3][r] = va.w;
            int gw = rowW0 + r;
            float4 vw = make_float4(0.f, 0.f, 0.f, 0.f);
            if (gw < N) vw = *(const float4*)(W + (size_t)gw * K + k0 + lcol);
            Ws[lcol + 0][r] = vw.x; Ws[lcol + 1][r] = vw.y;
            Ws[lcol + 2][r] = vw.z; Ws[lcol + 3][r] = vw.w;
        }
        __syncthreads();
#pragma unroll
        for (int k = 0; k < BK; k++) {
            float a[8], b[8];
#pragma unroll
            for (int i = 0; i < 4; i++) {
                a[i]     = As[k][ty * 4 + i];
                a[i + 4] = As[k][64 + ty * 4 + i];
                b[i]     = Ws[k][tx * 4 + i];
                b[i + 4] = Ws[k][64 + tx * 4 + i];
            }
#pragma unroll
            for (int i = 0; i < 8; i++)
#pragma unroll
                for (int j = 0; j < 8; j++)
                    acc[i][j] = fmaf(a[i], b[j], acc[i][j]);
        }
        __syncthreads();
    }

#pragma unroll
    for (int i = 0; i < 8; i++) {
        int mrow = rowA0 + ((i < 4) ? (ty * 4 + i) : (64 + ty * 4 + i - 4));
#pragma unroll
        for (int j = 0; j < 8; j++) {
            int ncol = rowW0 + ((j < 4) ? (tx * 4 + j) : (64 + tx * 4 + j - 4));
            if (ncol < N) {
                float v = acc[i][j];
                float* cp = C + (size_t)mrow * ldc + ncol;
                if (MODE == 1) {
                    v += bias[ncol];
                    v = fmaxf(v, 0.f) + log1pf(__expf(-fabsf(v)));
                }
                *cp = v;
            }
        }
    }
}

// ---------------------------------------------------------------------------
// Reduce split-K partials for xdbc
// ---------------------------------------------------------------------------
__global__ void k_reduce_x(const float* __restrict__ part, float* __restrict__ out)
{
    int idx = blockIdx.x * blockDim.x + threadIdx.x;
    if (idx >= ROWS * XDIM) return;
    float s = 0.f;
#pragma unroll
    for (int z = 0; z < SPLITK_X; z++) s += part[(size_t)z * ROWS * XDIM + idx];
    out[idx] = s;
}

// ---------------------------------------------------------------------------
// Depthwise causal conv (K=4) + SiLU
// ---------------------------------------------------------------------------
__global__ void k_conv(const float* __restrict__ proj,
                       const float* __restrict__ cw,
                       const float* __restrict__ cb,
                       float* __restrict__ u)
{
    int idx = blockIdx.x * blockDim.x + threadIdx.x;
    if (idx >= ROWS * EE) return;
    int e = idx % EE;
    int r = idx / EE;
    int t = r % LL;
    float acc = cb[e];
#pragma unroll
    for (int k = 0; k < KCONV; k++) {
        int tt = t - (KCONV - 1) + k;
        if (tt >= 0)
            acc = fmaf(cw[e * KCONV + k],
                       proj[(size_t)(r - (KCONV - 1) + k) * (2 * EE) + e], acc);
    }
    u[idx] = acc / (1.f + __expf(-acc));
}

// ---------------------------------------------------------------------------
// Selective scan (16 lanes per (b,e) group; lane = state index n)
// ---------------------------------------------------------------------------
__global__ void k_scan(const float* __restrict__ u,
                       const float* __restrict__ dt,
                       const float* __restrict__ xdbc,
                       const float* __restrict__ A_log,
                       const float* __restrict__ Dp,
                       const float* __restrict__ proj,
                       float* __restrict__ y)
{
    int gid  = (blockIdx.x * blockDim.x + threadIdx.x) >> 4;
    int lane = threadIdx.x & 15;
    if (gid >= BB * EE) return;
    int b = gid / EE, e = gid % EE;

    float An   = -__expf(A_log[e * NSTATE + lane]);
    float dval = Dp[e];
    float h = 0.f;

    const float* dtp = dt   + (size_t)b * LL * EE + e;
    const float* up  = u    + (size_t)b * LL * EE + e;
    const float* xp  = xdbc + (size_t)b * LL * XDIM;
    const float* gp  = proj + (size_t)b * LL * 2 * EE + EE + e;
    float*       yp  = y    + (size_t)b * LL * EE + e;

    for (int t = 0; t < LL; t++) {
        float dtv = __ldg(dtp + (size_t)t * EE);
        float uv  = __ldg(up  + (size_t)t * EE);
        float Bn  = __ldg(xp + (size_t)t * XDIM + RR + lane);
        float Cn  = __ldg(xp + (size_t)t * XDIM + RR + NSTATE + lane);
        float dA  = __expf(dtv * An);
        h = fmaf(h, dA, dtv * Bn * uv);
        float yv = h * Cn;
        yv += __shfl_xor_sync(0xffffffffu, yv, 1);
        yv += __shfl_xor_sync(0xffffffffu, yv, 2);
        yv += __shfl_xor_sync(0xffffffffu, yv, 4);
        yv += __shfl_xor_sync(0xffffffffu, yv, 8);
        if (lane == 0) {
            float g  = __ldg(gp + (size_t)t * 2 * EE);
            float sg = g / (1.f + __expf(-g));
            yp[(size_t)t * EE] = (yv + uv * dval) * sg;
        }
    }
}

// ---------------------------------------------------------------------------
// Mean-pool and classifier
// ---------------------------------------------------------------------------
__global__ void k_pool(const float* __restrict__ hn, float* __restrict__ pooled)
{
    int idx = blockIdx.x * blockDim.x + threadIdx.x;
    if (idx >= BB * DD) return;
    int b = idx / DD, d = idx % DD;
    float s = 0.f;
    for (int t = 0; t < LL; t++) s += hn[(size_t)(b * LL + t) * DD + d];
    pooled[idx] = s * (1.f / (float)LL);
}

__global__ void k_cls(const float* __restrict__ pooled,
                      const float* __restrict__ w,
                      const float* __restrict__ b,
                      float* __restrict__ out)
{
    int wid  = threadIdx.x >> 5;
    int lane = threadIdx.x & 31;
    if (wid >= BB * NCLS) return;
    int bb = wid / NCLS, c = wid % NCLS;
    float s = 0.f;
    for (int d = lane; d < DD; d += 32)
        s = fmaf(pooled[bb * DD + d], w[c * DD + d], s);
#pragma unroll
    for (int off = 16; off; off >>= 1) s += __shfl_xor_sync(0xffffffffu, s, off);
    if (lane == 0) out[bb * NCLS + c] = s + b[c];
}

// ---------------------------------------------------------------------------
// kernel_launch — graph-capturable, allocation-free
// ---------------------------------------------------------------------------
extern "C" void kernel_launch(void* const* d_in, const int* in_sizes, int n_in,
                              void* d_out, int out_size)
{
    const float* x       = (const float*)d_in[0];
    const float* proj_w  = (const float*)d_in[1];
    const float* proj_b  = (const float*)d_in[2];
    const float* norm_w  = (const float*)d_in[3];
    const float* in_w    = (const float*)d_in[4];
    const float* conv_w  = (const float*)d_in[5];
    const float* conv_b  = (const float*)d_in[6];
    const float* xproj_w = (const float*)d_in[7];
    const float* dt_w    = (const float*)d_in[8];
    const float* dt_b    = (const float*)d_in[9];
    const float* A_log   = (const float*)d_in[10];
    const float* D_param = (const float*)d_in[11];
    const float* out_w   = (const float*)d_in[12];
    const float* fnorm_w = (const float*)d_in[13];
    const float* cls_w   = (const float*)d_in[14];
    const float* cls_b   = (const float*)d_in[15];
    float* out = (float*)d_out;

    float *h_, *hn_, *proj_, *u_, *xdbc_, *xpart_, *dt_, *y_, *pooled_;
    cudaGetSymbolAddress((void**)&h_,      g_h);
    cudaGetSymbolAddress((void**)&hn_,     g_hn);
    cudaGetSymbolAddress((void**)&proj_,   g_proj);
    cudaGetSymbolAddress((void**)&u_,      g_u);
    cudaGetSymbolAddress((void**)&xdbc_,   g_xdbc);
    cudaGetSymbolAddress((void**)&xpart_,  g_xpart);
    cudaGetSymbolAddress((void**)&dt_,     g_dt);
    cudaGetSymbolAddress((void**)&y_,      g_y);
    cudaGetSymbolAddress((void**)&pooled_, g_pooled);

    // opt-in to >48KB dynamic smem for the mma GEMMs
    cudaFuncSetAttribute(gemm_mma<0>, cudaFuncAttributeMaxDynamicSharedMemorySize, MMA_SMEM);
    cudaFuncSetAttribute(gemm_mma<2>, cudaFuncAttributeMaxDynamicSharedMemorySize, MMA_SMEM);

    // h = x @ proj_w^T + proj_b
    k_proj<<<(ROWS * DD + 255) / 256, 256>>>(x, proj_w, proj_b, h_);

    for (int i = 0; i < NLAYER; i++) {
        // hn = rmsnorm(h, norm_w[i])
        k_rms<<<ROWS, 256>>>(h_, norm_w + i * DD, hn_);

        // proj = hn @ in_w[i]^T  (2048 x 3072, K=768) — mma.sync bf16x3
        {
            dim3 g(2 * EE / 128, ROWS / 128);
            gemm_mma<0><<<g, 256, MMA_SMEM>>>(hn_, DD,
                                              in_w + (size_t)i * 2 * EE * DD,
                                              proj_, 2 * EE, DD);
        }

        // u = silu(causal_conv(proj[:,:,:E]))
        k_conv<<<(ROWS * EE + 255) / 256, 256>>>(proj_, conv_w + i * EE * KCONV,
                                                 conv_b + i * EE, u_);

        // xdbc = u @ xproj_w[i]^T  (2048 x 80, K=1536) — fp32 split-K
        {
            dim3 g(1, ROWS / 128, SPLITK_X);
            gemm_nt<0><<<g, 256>>>(u_, EE, xproj_w + (size_t)i * XDIM * EE,
                                   nullptr, xpart_, XDIM,
                                   ROWS, XDIM, EE, EE / SPLITK_X);
            k_reduce_x<<<(ROWS * XDIM + 255) / 256, 256>>>(xpart_, xdbc_);
        }

        // dt = softplus(xdbc[:,:,:R] @ dt_w[i]^T + dt_b[i])  (2048 x 1536, K=48)
        {
            dim3 g(EE / 128, ROWS / 128);
            gemm_nt<1><<<g, 256>>>(xdbc_, XDIM, dt_w + (size_t)i * EE * RR,
                                   dt_b + i * EE, dt_, EE,
                                   ROWS, EE, RR, RR);
        }

        // selective scan (+ D skip + gate silu)
        k_scan<<<(BB * EE * 16) / 256, 256>>>(u_, dt_, xdbc_,
                                              A_log + i * EE * NSTATE,
                                              D_param + i * EE, proj_, y_);

        // h = h + y @ out_w[i]^T  (2048 x 768, K=1536) — mma.sync, residual
        {
            dim3 g(DD / 128, ROWS / 128);
            gemm_mma<2><<<g, 256, MMA_SMEM>>>(y_, EE,
                                              out_w + (size_t)i * DD * EE,
                                              h_, DD, EE);
        }
    }

    // final rmsnorm, mean pool, classifier
    k_rms<<<ROWS, 256>>>(h_, fnorm_w, hn_);
    k_pool<<<(BB * DD + 255) / 256, 256>>>(hn_, pooled_);
    k_cls<<<1, 320>>>(pooled_, cls_w, cls_b, out);
}